// round 9
// baseline (speedup 1.0000x reference)
#include <cuda_runtime.h>
#include <cuda_bf16.h>
#include <math.h>
#include <stdint.h>

// ---------------- problem constants ----------------
constexpr int SEQ   = 2048;
constexpr int HID   = 4096;
constexpr int NH    = 32;
constexpr int DN    = 128;   // nope dim
constexpr int DR    = 64;    // rope dim
constexpr int DV    = 128;   // v dim
constexpr int QKD   = NH * (DN + DR);   // 6144
constexpr int HVTOT = NH * DV;          // 4096
constexpr int FFN   = 16384;

// ---------------- scratch (static device, no allocs) ----------------
__device__ float g_h  [SEQ * HID];
__device__ float g_q  [SEQ * QKD];
__device__ float g_k  [SEQ * QKD];
__device__ float g_v  [SEQ * HVTOT];
__device__ float g_ctx[SEQ * HVTOT];
__device__ float g_x2 [SEQ * HID];
__device__ float g_h2 [SEQ * HID];
__device__ float g_ffn[SEQ * FFN];
// tf32-rounded weight copies
__device__ float g_wq[QKD * HID];
__device__ float g_wk[QKD * HID];
__device__ float g_wv[HVTOT * HID];
__device__ float g_wo[HID * HVTOT];
__device__ float g_w1[FFN * HID];
__device__ float g_w2[HID * FFN];

__device__ __forceinline__ uint32_t f2tf32(float f) {
    uint32_t u;
    asm("cvt.rna.tf32.f32 %0, %1;" : "=r"(u) : "f"(f));
    return u;
}
__device__ __forceinline__ float roundtf(float f) {
    return __uint_as_float(f2tf32(f));
}

// ---------------- weight rounding (f32 -> tf32-rounded f32) ----------------
__global__ void round_tf32_kernel(const float4* __restrict__ in,
                                  float4* __restrict__ out, int n4)
{
    int i = blockIdx.x * blockDim.x + threadIdx.x;
    if (i < n4) {
        float4 v = in[i];
        v.x = roundtf(v.x); v.y = roundtf(v.y);
        v.z = roundtf(v.z); v.w = roundtf(v.w);
        out[i] = v;
    }
}

// ---------------- layernorm (output tf32-rounded: feeds GEMM A) ----------------
__global__ void layernorm_kernel(const float* __restrict__ x,
                                 const float* __restrict__ wt,
                                 const float* __restrict__ bs,
                                 float* __restrict__ out)
{
    __shared__ float rs[8], rs2[8];
    int row = blockIdx.x, tid = threadIdx.x;
    const float4* xr = (const float4*)(x + (size_t)row * HID);
    float4 v[4];
    float s = 0.f, ss = 0.f;
#pragma unroll
    for (int it = 0; it < 4; it++) {
        v[it] = xr[tid + it * 256];
        s  += v[it].x + v[it].y + v[it].z + v[it].w;
        ss += v[it].x * v[it].x + v[it].y * v[it].y + v[it].z * v[it].z + v[it].w * v[it].w;
    }
#pragma unroll
    for (int off = 16; off; off >>= 1) {
        s  += __shfl_xor_sync(0xffffffffu, s, off);
        ss += __shfl_xor_sync(0xffffffffu, ss, off);
    }
    if ((tid & 31) == 0) { rs[tid >> 5] = s; rs2[tid >> 5] = ss; }
    __syncthreads();
    s = 0.f; ss = 0.f;
#pragma unroll
    for (int i = 0; i < 8; i++) { s += rs[i]; ss += rs2[i]; }
    float mean = s * (1.0f / HID);
    float var  = ss * (1.0f / HID) - mean * mean;
    float inv  = rsqrtf(var + 1e-6f);

    const float4* wv = (const float4*)wt;
    const float4* bv = (const float4*)bs;
    float4* ov = (float4*)(out + (size_t)row * HID);
#pragma unroll
    for (int it = 0; it < 4; it++) {
        float4 w4 = wv[tid + it * 256];
        float4 b4 = bv[tid + it * 256];
        float4 o4;
        o4.x = roundtf((v[it].x - mean) * inv * w4.x + b4.x);
        o4.y = roundtf((v[it].y - mean) * inv * w4.y + b4.y);
        o4.z = roundtf((v[it].z - mean) * inv * w4.z + b4.z);
        o4.w = roundtf((v[it].w - mean) * inv * w4.w + b4.w);
        ov[tid + it * 256] = o4;
    }
}

// ---------------- tf32 tensor-core GEMM (no in-loop CVT) ----------------
// C[M,N] = act(A[M,K] @ B[N,K]^T) (+ residual); A,B already tf32-rounded.
// 128x128x32 tile, 256 threads (8 warps, 2x4), warp tile 64x32 (4x4 m16n8k8),
// cp.async double buffering, fp32 accumulate.
constexpr int GLD = 36;                  // smem row stride (floats), pad 4
constexpr int G_TILE_FLOATS = 128 * GLD; // per matrix per buffer
constexpr int G_SMEM_BYTES  = 2 * 2 * G_TILE_FLOATS * 4;  // 73728

__device__ __forceinline__ void cpa16(uint32_t dst, const float* src) {
    asm volatile("cp.async.cg.shared.global [%0], [%1], 16;\n" :: "r"(dst), "l"(src));
}
__device__ __forceinline__ void mma_tf32(float* c, const uint32_t* a, const uint32_t* b) {
    asm volatile(
        "mma.sync.aligned.m16n8k8.row.col.f32.tf32.tf32.f32 "
        "{%0,%1,%2,%3}, {%4,%5,%6,%7}, {%8,%9}, {%0,%1,%2,%3};\n"
        : "+f"(c[0]), "+f"(c[1]), "+f"(c[2]), "+f"(c[3])
        : "r"(a[0]), "r"(a[1]), "r"(a[2]), "r"(a[3]), "r"(b[0]), "r"(b[1]));
}

__global__ __launch_bounds__(256, 2)
void tf32_gemm_kernel(const float* __restrict__ A,
                      const float* __restrict__ B,
                      float* __restrict__ C,
                      int M, int N, int K,
                      const float* __restrict__ residual,
                      int act)
{
    extern __shared__ __align__(16) float gsm[];
    float* Asm = gsm;                       // [2][128][36]
    float* Bsm = gsm + 2 * G_TILE_FLOATS;   // [2][128][36]

    int tid  = threadIdx.x;
    int warp = tid >> 5, lane = tid & 31;
    int wm = warp >> 2;         // 0..1
    int wn = warp & 3;          // 0..3
    int grp = lane >> 2;        // 0..7
    int qid = lane & 3;         // 0..3
    int bm = blockIdx.y * 128;
    int bn = blockIdx.x * 128;

    const float* Ab = A + (size_t)bm * K;
    const float* Bb = B + (size_t)bn * K;

    uint32_t sA = (uint32_t)__cvta_generic_to_shared(Asm);
    uint32_t sB = (uint32_t)__cvta_generic_to_shared(Bsm);

    int ldrow = tid >> 3;          // 0..31
    int ldc4  = (tid & 7) * 4;     // k-offset in floats

    float acc[4][4][4];
#pragma unroll
    for (int mt = 0; mt < 4; mt++)
#pragma unroll
        for (int nt = 0; nt < 4; nt++)
#pragma unroll
            for (int r = 0; r < 4; r++) acc[mt][nt][r] = 0.f;

    int NT = K >> 5;   // K/32

    // prefetch tile 0 into buffer 0
    {
        uint32_t dA = sA, dB = sB;
#pragma unroll
        for (int i = 0; i < 4; i++) {
            int row = ldrow + i * 32;
            cpa16(dA + (row * GLD + ldc4) * 4, Ab + (size_t)row * K + ldc4);
            cpa16(dB + (row * GLD + ldc4) * 4, Bb + (size_t)row * K + ldc4);
        }
        asm volatile("cp.async.commit_group;\n");
    }

    for (int t = 0; t < NT; t++) {
        asm volatile("cp.async.wait_group 0;\n" ::: "memory");
        __syncthreads();

        if (t + 1 < NT) {
            int k0n = (t + 1) << 5;
            uint32_t dA = sA + ((t + 1) & 1) * G_TILE_FLOATS * 4;
            uint32_t dB = sB + ((t + 1) & 1) * G_TILE_FLOATS * 4;
#pragma unroll
            for (int i = 0; i < 4; i++) {
                int row = ldrow + i * 32;
                cpa16(dA + (row * GLD + ldc4) * 4, Ab + (size_t)row * K + k0n + ldc4);
                cpa16(dB + (row * GLD + ldc4) * 4, Bb + (size_t)row * K + k0n + ldc4);
            }
            asm volatile("cp.async.commit_group;\n");
        }

        const uint32_t* Asb = (const uint32_t*)(Asm + (t & 1) * G_TILE_FLOATS);
        const uint32_t* Bsb = (const uint32_t*)(Bsm + (t & 1) * G_TILE_FLOATS);

#pragma unroll
        for (int ks = 0; ks < 4; ks++) {
            int k0 = ks * 8;
            uint32_t af[4][4], bf[4][2];
#pragma unroll
            for (int mt = 0; mt < 4; mt++) {
                const uint32_t* base = Asb + (wm * 64 + mt * 16 + grp) * GLD + k0 + qid;
                af[mt][0] = base[0];
                af[mt][1] = base[8 * GLD];
                af[mt][2] = base[4];
                af[mt][3] = base[8 * GLD + 4];
            }
#pragma unroll
            for (int nt = 0; nt < 4; nt++) {
                const uint32_t* base = Bsb + (wn * 32 + nt * 8 + grp) * GLD + k0 + qid;
                bf[nt][0] = base[0];
                bf[nt][1] = base[4];
            }
#pragma unroll
            for (int mt = 0; mt < 4; mt++)
#pragma unroll
                for (int nt = 0; nt < 4; nt++)
                    mma_tf32(acc[mt][nt], af[mt], bf[nt]);
        }
        __syncthreads();
    }

    // epilogue
#pragma unroll
    for (int mt = 0; mt < 4; mt++) {
#pragma unroll
        for (int half = 0; half < 2; half++) {
            int r = bm + wm * 64 + mt * 16 + grp + half * 8;
            size_t rowoff = (size_t)r * N;
#pragma unroll
            for (int nt = 0; nt < 4; nt++) {
                int c = bn + wn * 32 + nt * 8 + qid * 2;
                float v0 = acc[mt][nt][half * 2 + 0];
                float v1 = acc[mt][nt][half * 2 + 1];
                if (act == 1) {
                    // silu, then round: output feeds the next GEMM's A operand
                    v0 = roundtf(v0 * (1.0f / (1.0f + __expf(-v0))));
                    v1 = roundtf(v1 * (1.0f / (1.0f + __expf(-v1))));
                }
                if (residual != nullptr) {
                    float2 rv = *(const float2*)(residual + rowoff + c);
                    v0 += rv.x; v1 += rv.y;
                }
                *(float2*)(C + rowoff + c) = make_float2(v0, v1);
            }
        }
    }
}

// ---------------- RoPE (in place on q and k rope halves) ----------------
__global__ void rope_kernel(float* __restrict__ q, float* __restrict__ k)
{
    int s = blockIdx.x;
    int h = blockIdx.y;
    float* buf = (blockIdx.z == 0) ? q : k;
    int i = threadIdx.x;   // 0..31
    size_t base = (size_t)s * QKD + NH * DN + (size_t)h * DR;
    float invf = __powf(10000.0f, -(2.0f * (float)i) / (float)DR);
    float ang = (float)s * invf;
    float sn, cs;
    sincosf(ang, &sn, &cs);
    float x1 = buf[base + i];
    float x2 = buf[base + 32 + i];
    buf[base + i]      = x1 * cs - x2 * sn;
    buf[base + 32 + i] = x1 * sn + x2 * cs;
}

// ---------------- flash attention ----------------
// grid: (SEQ/64, NH). block 256. smem: Qt[192][68], Kt[192][68], Vs[64][128], Ps[64][64]
constexpr int QT_LD = 68;
constexpr int FA_SMEM_FLOATS = 192 * QT_LD * 2 + 64 * 128 + 64 * 64;
constexpr int FA_SMEM_BYTES  = FA_SMEM_FLOATS * 4;   // 153600

__global__ void flash_attn_kernel(const float* __restrict__ q,
                                  const float* __restrict__ k,
                                  const float* __restrict__ v,
                                  float* __restrict__ ctx)
{
    extern __shared__ __align__(16) float sm[];
    float* Qt = sm;                       // 192 x 68
    float* Kt = Qt + 192 * QT_LD;         // 192 x 68
    float* Vs = Kt + 192 * QT_LD;         // 64 x 128
    float* Ps = Vs + 64 * 128;            // 64 x 64

    int qb = blockIdx.x;
    int h  = blockIdx.y;
    int tid = threadIdx.x;
    int warp = tid >> 5;
    int lane = tid & 31;
    int tx = tid & 15;
    int ty = tid >> 4;
    int row0 = qb * 64;
    int rbase = warp * 8;

    const float scale_n = 0.08838834764831845f;  // 1/sqrt(128)
    const float scale_r = 0.125f;                // 1/sqrt(64)

    for (int e = tid; e < 64 * 128; e += 256) {
        int i = e >> 7, d = e & 127;
        Qt[d * QT_LD + i] = q[(size_t)(row0 + i) * QKD + h * DN + d] * scale_n;
    }
    for (int e = tid; e < 64 * 64; e += 256) {
        int i = e >> 6, d = e & 63;
        Qt[(128 + d) * QT_LD + i] =
            q[(size_t)(row0 + i) * QKD + NH * DN + h * DR + d] * scale_r;
    }

    float m_state[8], l_state[8];
    float o[8][4];
#pragma unroll
    for (int rr = 0; rr < 8; rr++) {
        m_state[rr] = -1e30f;
        l_state[rr] = 0.f;
        o[rr][0] = o[rr][1] = o[rr][2] = o[rr][3] = 0.f;
    }

    for (int kb = 0; kb <= qb; kb++) {
        int krow0 = kb * 64;
        __syncthreads();
        for (int e = tid; e < 64 * 128; e += 256) {
            int j = e >> 7, d = e & 127;
            Kt[d * QT_LD + j] = k[(size_t)(krow0 + j) * QKD + h * DN + d];
        }
        for (int e = tid; e < 64 * 64; e += 256) {
            int j = e >> 6, d = e & 63;
            Kt[(128 + d) * QT_LD + j] =
                k[(size_t)(krow0 + j) * QKD + NH * DN + h * DR + d];
        }
        for (int e = tid; e < 64 * 32; e += 256) {
            int j = e >> 5, d4 = e & 31;
            ((float4*)(Vs + j * 128))[d4] =
                *(const float4*)(v + (size_t)(krow0 + j) * HVTOT + h * DV + d4 * 4);
        }
        __syncthreads();

        float sc[4][4];
#pragma unroll
        for (int i = 0; i < 4; i++)
#pragma unroll
            for (int j = 0; j < 4; j++) sc[i][j] = 0.f;

#pragma unroll 4
        for (int d = 0; d < 192; d++) {
            float4 aq = *(const float4*)&Qt[d * QT_LD + ty * 4];
            float4 bk = *(const float4*)&Kt[d * QT_LD + tx * 4];
            float ar[4] = {aq.x, aq.y, aq.z, aq.w};
            float br[4] = {bk.x, bk.y, bk.z, bk.w};
#pragma unroll
            for (int i = 0; i < 4; i++)
#pragma unroll
                for (int j = 0; j < 4; j++)
                    sc[i][j] += ar[i] * br[j];
        }

        bool diag = (kb == qb);
#pragma unroll
        for (int i = 0; i < 4; i++) {
            int r = ty * 4 + i;
            float4 w4 = make_float4(sc[i][0], sc[i][1], sc[i][2], sc[i][3]);
            if (diag) {
                if (tx * 4 + 0 > r) w4.x = -1e30f;
                if (tx * 4 + 1 > r) w4.y = -1e30f;
                if (tx * 4 + 2 > r) w4.z = -1e30f;
                if (tx * 4 + 3 > r) w4.w = -1e30f;
            }
            *(float4*)&Ps[r * 64 + tx * 4] = w4;
        }
        __syncwarp();

        float alpha[8];
#pragma unroll
        for (int rr = 0; rr < 8; rr++) {
            int r = rbase + rr;
            float s0 = Ps[r * 64 + lane];
            float s1 = Ps[r * 64 + 32 + lane];
            float mx = fmaxf(s0, s1);
#pragma unroll
            for (int off = 16; off; off >>= 1)
                mx = fmaxf(mx, __shfl_xor_sync(0xffffffffu, mx, off));
            float m_new = fmaxf(m_state[rr], mx);
            float a_ = __expf(m_state[rr] - m_new);
            float e0 = __expf(s0 - m_new);
            float e1 = __expf(s1 - m_new);
            Ps[r * 64 + lane]      = e0;
            Ps[r * 64 + 32 + lane] = e1;
            float rsum = e0 + e1;
#pragma unroll
            for (int off = 16; off; off >>= 1)
                rsum += __shfl_xor_sync(0xffffffffu, rsum, off);
            l_state[rr] = l_state[rr] * a_ + rsum;
            m_state[rr] = m_new;
            alpha[rr] = a_;
        }
        __syncwarp();

#pragma unroll
        for (int rr = 0; rr < 8; rr++) {
            o[rr][0] *= alpha[rr]; o[rr][1] *= alpha[rr];
            o[rr][2] *= alpha[rr]; o[rr][3] *= alpha[rr];
        }
#pragma unroll 2
        for (int j = 0; j < 64; j++) {
            float4 vv = *(const float4*)&Vs[j * 128 + lane * 4];
#pragma unroll
            for (int rr = 0; rr < 8; rr++) {
                float p = Ps[(rbase + rr) * 64 + j];
                o[rr][0] += p * vv.x;
                o[rr][1] += p * vv.y;
                o[rr][2] += p * vv.z;
                o[rr][3] += p * vv.w;
            }
        }
    }

    // ctx feeds the O-projection GEMM A operand -> round to tf32 here
#pragma unroll
    for (int rr = 0; rr < 8; rr++) {
        float invl = 1.0f / l_state[rr];
        float4 ov = make_float4(roundtf(o[rr][0] * invl), roundtf(o[rr][1] * invl),
                                roundtf(o[rr][2] * invl), roundtf(o[rr][3] * invl));
        *(float4*)(ctx + (size_t)(row0 + rbase + rr) * HVTOT + h * DV + lane * 4) = ov;
    }
}

// ---------------- launcher ----------------
extern "C" void kernel_launch(void* const* d_in, const int* in_sizes, int n_in,
                              void* d_out, int out_size)
{
    const float* x    = (const float*)d_in[0];
    // d_in[1] = attention_mask: exactly causal -1e9 triu -> handled analytically
    const float* w_q  = (const float*)d_in[2];
    const float* w_k  = (const float*)d_in[3];
    const float* w_v  = (const float*)d_in[4];
    const float* w_o  = (const float*)d_in[5];
    const float* ln1w = (const float*)d_in[6];
    const float* ln1b = (const float*)d_in[7];
    const float* ln2w = (const float*)d_in[8];
    const float* ln2b = (const float*)d_in[9];
    const float* w1   = (const float*)d_in[10];
    const float* w2   = (const float*)d_in[11];
    float* out = (float*)d_out;

    float *h, *q, *k, *v, *ctx, *x2, *h2, *ffn;
    float *wq, *wk, *wv, *wo, *w1r, *w2r;
    cudaGetSymbolAddress((void**)&h,   g_h);
    cudaGetSymbolAddress((void**)&q,   g_q);
    cudaGetSymbolAddress((void**)&k,   g_k);
    cudaGetSymbolAddress((void**)&v,   g_v);
    cudaGetSymbolAddress((void**)&ctx, g_ctx);
    cudaGetSymbolAddress((void**)&x2,  g_x2);
    cudaGetSymbolAddress((void**)&h2,  g_h2);
    cudaGetSymbolAddress((void**)&ffn, g_ffn);
    cudaGetSymbolAddress((void**)&wq,  g_wq);
    cudaGetSymbolAddress((void**)&wk,  g_wk);
    cudaGetSymbolAddress((void**)&wv,  g_wv);
    cudaGetSymbolAddress((void**)&wo,  g_wo);
    cudaGetSymbolAddress((void**)&w1r, g_w1);
    cudaGetSymbolAddress((void**)&w2r, g_w2);

    cudaFuncSetAttribute(flash_attn_kernel,
                         cudaFuncAttributeMaxDynamicSharedMemorySize, FA_SMEM_BYTES);
    cudaFuncSetAttribute(tf32_gemm_kernel,
                         cudaFuncAttributeMaxDynamicSharedMemorySize, G_SMEM_BYTES);

    // 0. round weights to tf32 once (RNA), so GEMM needs no in-loop CVT
    auto round_launch = [](const float* src, float* dst, size_t n) {
        int n4 = (int)(n / 4);
        round_tf32_kernel<<<(n4 + 255) / 256, 256>>>((const float4*)src, (float4*)dst, n4);
    };
    round_launch(w_q, wq, (size_t)QKD * HID);
    round_launch(w_k, wk, (size_t)QKD * HID);
    round_launch(w_v, wv, (size_t)HVTOT * HID);
    round_launch(w_o, wo, (size_t)HID * HVTOT);
    round_launch(w1,  w1r, (size_t)FFN * HID);
    round_launch(w2,  w2r, (size_t)HID * FFN);

    // 1. ln1 (output tf32-rounded)
    layernorm_kernel<<<SEQ, 256>>>(x, ln1w, ln1b, h);
    // 2-4. q, k, v projections
    tf32_gemm_kernel<<<dim3(QKD / 128, SEQ / 128), 256, G_SMEM_BYTES>>>(h, wq, q, SEQ, QKD, HID, nullptr, 0);
    tf32_gemm_kernel<<<dim3(QKD / 128, SEQ / 128), 256, G_SMEM_BYTES>>>(h, wk, k, SEQ, QKD, HID, nullptr, 0);
    tf32_gemm_kernel<<<dim3(HVTOT / 128, SEQ / 128), 256, G_SMEM_BYTES>>>(h, wv, v, SEQ, HVTOT, HID, nullptr, 0);
    // 5. rope on q and k
    rope_kernel<<<dim3(SEQ, NH, 2), 32>>>(q, k);
    // 6. attention (ctx output tf32-rounded)
    flash_attn_kernel<<<dim3(SEQ / 64, NH), 256, FA_SMEM_BYTES>>>(q, k, v, ctx);
    // 7. o projection + residual(x)
    tf32_gemm_kernel<<<dim3(HID / 128, SEQ / 128), 256, G_SMEM_BYTES>>>(ctx, wo, x2, SEQ, HID, HVTOT, x, 0);
    // 8. ln2 (output tf32-rounded)
    layernorm_kernel<<<SEQ, 256>>>(x2, ln2w, ln2b, h2);
    // 9. ffn up + silu (+ tf32 rounding of output)
    tf32_gemm_kernel<<<dim3(FFN / 128, SEQ / 128), 256, G_SMEM_BYTES>>>(h2, w1r, ffn, SEQ, FFN, HID, nullptr, 1);
    // 10. ffn down + residual(x2) -> out
    tf32_gemm_kernel<<<dim3(HID / 128, SEQ / 128), 256, G_SMEM_BYTES>>>(ffn, w2r, out, SEQ, HID, FFN, x2, 0);
}

// round 13
// speedup vs baseline: 1.2576x; 1.2576x over previous
#include <cuda_runtime.h>
#include <cuda_bf16.h>
#include <math.h>
#include <stdint.h>

// ---------------- problem constants ----------------
constexpr int SEQ   = 2048;
constexpr int HID   = 4096;
constexpr int NH    = 32;
constexpr int DN    = 128;   // nope dim
constexpr int DR    = 64;    // rope dim
constexpr int DV    = 128;   // v dim
constexpr int QKD   = NH * (DN + DR);   // 6144
constexpr int HVTOT = NH * DV;          // 4096
constexpr int FFN   = 16384;

// ---------------- scratch (static device, no allocs) ----------------
__device__ float g_h  [SEQ * HID];
__device__ float g_q  [SEQ * QKD];
__device__ float g_k  [SEQ * QKD];
__device__ float g_v  [SEQ * HVTOT];
__device__ float g_ctx[SEQ * HVTOT];
__device__ float g_x2 [SEQ * HID];
__device__ float g_h2 [SEQ * HID];
__device__ float g_ffn[SEQ * FFN];

// ---------------- layernorm ----------------
__global__ void layernorm_kernel(const float* __restrict__ x,
                                 const float* __restrict__ wt,
                                 const float* __restrict__ bs,
                                 float* __restrict__ out)
{
    __shared__ float rs[8], rs2[8];
    int row = blockIdx.x, tid = threadIdx.x;
    const float4* xr = (const float4*)(x + (size_t)row * HID);
    float4 v[4];
    float s = 0.f, ss = 0.f;
#pragma unroll
    for (int it = 0; it < 4; it++) {
        v[it] = xr[tid + it * 256];
        s  += v[it].x + v[it].y + v[it].z + v[it].w;
        ss += v[it].x * v[it].x + v[it].y * v[it].y + v[it].z * v[it].z + v[it].w * v[it].w;
    }
#pragma unroll
    for (int off = 16; off; off >>= 1) {
        s  += __shfl_xor_sync(0xffffffffu, s, off);
        ss += __shfl_xor_sync(0xffffffffu, ss, off);
    }
    if ((tid & 31) == 0) { rs[tid >> 5] = s; rs2[tid >> 5] = ss; }
    __syncthreads();
    s = 0.f; ss = 0.f;
#pragma unroll
    for (int i = 0; i < 8; i++) { s += rs[i]; ss += rs2[i]; }
    float mean = s * (1.0f / HID);
    float var  = ss * (1.0f / HID) - mean * mean;
    float inv  = rsqrtf(var + 1e-6f);

    const float4* wv = (const float4*)wt;
    const float4* bv = (const float4*)bs;
    float4* ov = (float4*)(out + (size_t)row * HID);
#pragma unroll
    for (int it = 0; it < 4; it++) {
        float4 w4 = wv[tid + it * 256];
        float4 b4 = bv[tid + it * 256];
        float4 o4;
        o4.x = (v[it].x - mean) * inv * w4.x + b4.x;
        o4.y = (v[it].y - mean) * inv * w4.y + b4.y;
        o4.z = (v[it].z - mean) * inv * w4.z + b4.z;
        o4.w = (v[it].w - mean) * inv * w4.w + b4.w;
        ov[tid + it * 256] = o4;
    }
}

// ---------------- tf32 tensor-core GEMM ----------------
// C[M,N] = act(A[M,K] @ B[N,K]^T) (+ residual)
// 128x128x32 tile, 256 threads (8 warps, 2x4), warp tile 64x32 (4x4 m16n8k8),
// 3-stage cp.async pipeline (wait_group 1), cvt.rna.tf32 fragments, fp32 accum.
constexpr int GLD = 36;                  // smem row stride (floats), pad 4
constexpr int G_TILE_FLOATS = 128 * GLD; // per matrix per stage
constexpr int G_STAGES = 3;
constexpr int G_SMEM_BYTES = G_STAGES * 2 * G_TILE_FLOATS * 4;  // 110592

__device__ __forceinline__ void cpa16(uint32_t dst, const float* src) {
    asm volatile("cp.async.cg.shared.global [%0], [%1], 16;\n" :: "r"(dst), "l"(src));
}
__device__ __forceinline__ uint32_t f2tf32(float f) {
    uint32_t u;
    asm("cvt.rna.tf32.f32 %0, %1;" : "=r"(u) : "f"(f));
    return u;
}
__device__ __forceinline__ void mma_tf32(float* c, const uint32_t* a, const uint32_t* b) {
    asm volatile(
        "mma.sync.aligned.m16n8k8.row.col.f32.tf32.tf32.f32 "
        "{%0,%1,%2,%3}, {%4,%5,%6,%7}, {%8,%9}, {%0,%1,%2,%3};\n"
        : "+f"(c[0]), "+f"(c[1]), "+f"(c[2]), "+f"(c[3])
        : "r"(a[0]), "r"(a[1]), "r"(a[2]), "r"(a[3]), "r"(b[0]), "r"(b[1]));
}

__global__ __launch_bounds__(256, 1)
void tf32_gemm_kernel(const float* __restrict__ A,
                      const float* __restrict__ B,
                      float* __restrict__ C,
                      int M, int N, int K,
                      const float* __restrict__ residual,
                      int act)
{
    extern __shared__ __align__(16) float gsm[];
    // layout: stage s -> A at gsm + s*2*TILE, B at gsm + s*2*TILE + TILE

    int tid  = threadIdx.x;
    int warp = tid >> 5, lane = tid & 31;
    int wm = warp >> 2;         // 0..1
    int wn = warp & 3;          // 0..3
    int grp = lane >> 2;        // 0..7
    int qid = lane & 3;         // 0..3
    int bm = blockIdx.y * 128;
    int bn = blockIdx.x * 128;

    const float* Ab = A + (size_t)bm * K;
    const float* Bb = B + (size_t)bn * K;

    uint32_t sbase = (uint32_t)__cvta_generic_to_shared(gsm);

    int ldrow = tid >> 3;          // 0..31
    int ldc4  = (tid & 7) * 4;     // k-offset in floats

    float acc[4][4][4];
#pragma unroll
    for (int mt = 0; mt < 4; mt++)
#pragma unroll
        for (int nt = 0; nt < 4; nt++)
#pragma unroll
            for (int r = 0; r < 4; r++) acc[mt][nt][r] = 0.f;

    int NT = K >> 5;   // K/32  (>= 32 for all our shapes)

    auto prefetch = [&](int t) {
        int stage = t % G_STAGES;
        int k0 = t << 5;
        uint32_t dA = sbase + (stage * 2 * G_TILE_FLOATS) * 4;
        uint32_t dB = dA + G_TILE_FLOATS * 4;
#pragma unroll
        for (int i = 0; i < 4; i++) {
            int row = ldrow + i * 32;
            cpa16(dA + (row * GLD + ldc4) * 4, Ab + (size_t)row * K + k0 + ldc4);
            cpa16(dB + (row * GLD + ldc4) * 4, Bb + (size_t)row * K + k0 + ldc4);
        }
        asm volatile("cp.async.commit_group;\n");
    };

    prefetch(0);
    prefetch(1);

    for (int t = 0; t < NT; t++) {
        if (t + 1 < NT)
            asm volatile("cp.async.wait_group 1;\n" ::: "memory");
        else
            asm volatile("cp.async.wait_group 0;\n" ::: "memory");
        __syncthreads();   // stage t visible to all; prev compute done before reuse

        if (t + 2 < NT) prefetch(t + 2);

        int stage = t % G_STAGES;
        const float* Asb = gsm + stage * 2 * G_TILE_FLOATS;
        const float* Bsb = Asb + G_TILE_FLOATS;

#pragma unroll
        for (int ks = 0; ks < 4; ks++) {
            int k0 = ks * 8;
            uint32_t af[4][4], bf[4][2];
#pragma unroll
            for (int mt = 0; mt < 4; mt++) {
                const float* base = Asb + (wm * 64 + mt * 16 + grp) * GLD + k0 + qid;
                af[mt][0] = f2tf32(base[0]);
                af[mt][1] = f2tf32(base[8 * GLD]);
                af[mt][2] = f2tf32(base[4]);
                af[mt][3] = f2tf32(base[8 * GLD + 4]);
            }
#pragma unroll
            for (int nt = 0; nt < 4; nt++) {
                const float* base = Bsb + (wn * 32 + nt * 8 + grp) * GLD + k0 + qid;
                bf[nt][0] = f2tf32(base[0]);
                bf[nt][1] = f2tf32(base[4]);
            }
#pragma unroll
            for (int mt = 0; mt < 4; mt++)
#pragma unroll
                for (int nt = 0; nt < 4; nt++)
                    mma_tf32(acc[mt][nt], af[mt], bf[nt]);
        }
    }

    // epilogue
#pragma unroll
    for (int mt = 0; mt < 4; mt++) {
#pragma unroll
        for (int half = 0; half < 2; half++) {
            int r = bm + wm * 64 + mt * 16 + grp + half * 8;
            size_t rowoff = (size_t)r * N;
#pragma unroll
            for (int nt = 0; nt < 4; nt++) {
                int c = bn + wn * 32 + nt * 8 + qid * 2;
                float v0 = acc[mt][nt][half * 2 + 0];
                float v1 = acc[mt][nt][half * 2 + 1];
                if (act == 1) {
                    v0 = v0 * (1.0f / (1.0f + __expf(-v0)));
                    v1 = v1 * (1.0f / (1.0f + __expf(-v1)));
                }
                if (residual != nullptr) {
                    float2 rv = *(const float2*)(residual + rowoff + c);
                    v0 += rv.x; v1 += rv.y;
                }
                *(float2*)(C + rowoff + c) = make_float2(v0, v1);
            }
        }
    }
}

// ---------------- RoPE (in place on q and k rope halves) ----------------
__global__ void rope_kernel(float* __restrict__ q, float* __restrict__ k)
{
    int s = blockIdx.x;
    int h = blockIdx.y;
    float* buf = (blockIdx.z == 0) ? q : k;
    int i = threadIdx.x;   // 0..31
    size_t base = (size_t)s * QKD + NH * DN + (size_t)h * DR;
    float invf = __powf(10000.0f, -(2.0f * (float)i) / (float)DR);
    float ang = (float)s * invf;
    float sn, cs;
    sincosf(ang, &sn, &cs);
    float x1 = buf[base + i];
    float x2 = buf[base + 32 + i];
    buf[base + i]      = x1 * cs - x2 * sn;
    buf[base + 32 + i] = x1 * sn + x2 * cs;
}

// ---------------- flash attention ----------------
// grid: (SEQ/64, NH). block 256. smem: Qt[192][68], Kt[192][68], Vs[64][128], Ps[64][64]
constexpr int QT_LD = 68;
constexpr int FA_SMEM_FLOATS = 192 * QT_LD * 2 + 64 * 128 + 64 * 64;
constexpr int FA_SMEM_BYTES  = FA_SMEM_FLOATS * 4;   // 153600

__global__ void flash_attn_kernel(const float* __restrict__ q,
                                  const float* __restrict__ k,
                                  const float* __restrict__ v,
                                  float* __restrict__ ctx)
{
    extern __shared__ __align__(16) float sm[];
    float* Qt = sm;                       // 192 x 68
    float* Kt = Qt + 192 * QT_LD;         // 192 x 68
    float* Vs = Kt + 192 * QT_LD;         // 64 x 128
    float* Ps = Vs + 64 * 128;            // 64 x 64

    int qb = blockIdx.x;
    int h  = blockIdx.y;
    int tid = threadIdx.x;
    int warp = tid >> 5;
    int lane = tid & 31;
    int tx = tid & 15;
    int ty = tid >> 4;
    int row0 = qb * 64;
    int rbase = warp * 8;

    const float scale_n = 0.08838834764831845f;  // 1/sqrt(128)
    const float scale_r = 0.125f;                // 1/sqrt(64)

    for (int e = tid; e < 64 * 128; e += 256) {
        int i = e >> 7, d = e & 127;
        Qt[d * QT_LD + i] = q[(size_t)(row0 + i) * QKD + h * DN + d] * scale_n;
    }
    for (int e = tid; e < 64 * 64; e += 256) {
        int i = e >> 6, d = e & 63;
        Qt[(128 + d) * QT_LD + i] =
            q[(size_t)(row0 + i) * QKD + NH * DN + h * DR + d] * scale_r;
    }

    float m_state[8], l_state[8];
    float o[8][4];
#pragma unroll
    for (int rr = 0; rr < 8; rr++) {
        m_state[rr] = -1e30f;
        l_state[rr] = 0.f;
        o[rr][0] = o[rr][1] = o[rr][2] = o[rr][3] = 0.f;
    }

    for (int kb = 0; kb <= qb; kb++) {
        int krow0 = kb * 64;
        __syncthreads();
        for (int e = tid; e < 64 * 128; e += 256) {
            int j = e >> 7, d = e & 127;
            Kt[d * QT_LD + j] = k[(size_t)(krow0 + j) * QKD + h * DN + d];
        }
        for (int e = tid; e < 64 * 64; e += 256) {
            int j = e >> 6, d = e & 63;
            Kt[(128 + d) * QT_LD + j] =
                k[(size_t)(krow0 + j) * QKD + NH * DN + h * DR + d];
        }
        for (int e = tid; e < 64 * 32; e += 256) {
            int j = e >> 5, d4 = e & 31;
            ((float4*)(Vs + j * 128))[d4] =
                *(const float4*)(v + (size_t)(krow0 + j) * HVTOT + h * DV + d4 * 4);
        }
        __syncthreads();

        float sc[4][4];
#pragma unroll
        for (int i = 0; i < 4; i++)
#pragma unroll
            for (int j = 0; j < 4; j++) sc[i][j] = 0.f;

#pragma unroll 4
        for (int d = 0; d < 192; d++) {
            float4 aq = *(const float4*)&Qt[d * QT_LD + ty * 4];
            float4 bk = *(const float4*)&Kt[d * QT_LD + tx * 4];
            float ar[4] = {aq.x, aq.y, aq.z, aq.w};
            float br[4] = {bk.x, bk.y, bk.z, bk.w};
#pragma unroll
            for (int i = 0; i < 4; i++)
#pragma unroll
                for (int j = 0; j < 4; j++)
                    sc[i][j] += ar[i] * br[j];
        }

        bool diag = (kb == qb);
#pragma unroll
        for (int i = 0; i < 4; i++) {
            int r = ty * 4 + i;
            float4 w4 = make_float4(sc[i][0], sc[i][1], sc[i][2], sc[i][3]);
            if (diag) {
                if (tx * 4 + 0 > r) w4.x = -1e30f;
                if (tx * 4 + 1 > r) w4.y = -1e30f;
                if (tx * 4 + 2 > r) w4.z = -1e30f;
                if (tx * 4 + 3 > r) w4.w = -1e30f;
            }
            *(float4*)&Ps[r * 64 + tx * 4] = w4;
        }
        __syncwarp();

        float alpha[8];
#pragma unroll
        for (int rr = 0; rr < 8; rr++) {
            int r = rbase + rr;
            float s0 = Ps[r * 64 + lane];
            float s1 = Ps[r * 64 + 32 + lane];
            float mx = fmaxf(s0, s1);
#pragma unroll
            for (int off = 16; off; off >>= 1)
                mx = fmaxf(mx, __shfl_xor_sync(0xffffffffu, mx, off));
            float m_new = fmaxf(m_state[rr], mx);
            float a_ = __expf(m_state[rr] - m_new);
            float e0 = __expf(s0 - m_new);
            float e1 = __expf(s1 - m_new);
            Ps[r * 64 + lane]      = e0;
            Ps[r * 64 + 32 + lane] = e1;
            float rsum = e0 + e1;
#pragma unroll
            for (int off = 16; off; off >>= 1)
                rsum += __shfl_xor_sync(0xffffffffu, rsum, off);
            l_state[rr] = l_state[rr] * a_ + rsum;
            m_state[rr] = m_new;
            alpha[rr] = a_;
        }
        __syncwarp();

#pragma unroll
        for (int rr = 0; rr < 8; rr++) {
            o[rr][0] *= alpha[rr]; o[rr][1] *= alpha[rr];
            o[rr][2] *= alpha[rr]; o[rr][3] *= alpha[rr];
        }
#pragma unroll 2
        for (int j = 0; j < 64; j++) {
            float4 vv = *(const float4*)&Vs[j * 128 + lane * 4];
#pragma unroll
            for (int rr = 0; rr < 8; rr++) {
                float p = Ps[(rbase + rr) * 64 + j];
                o[rr][0] += p * vv.x;
                o[rr][1] += p * vv.y;
                o[rr][2] += p * vv.z;
                o[rr][3] += p * vv.w;
            }
        }
    }

#pragma unroll
    for (int rr = 0; rr < 8; rr++) {
        float invl = 1.0f / l_state[rr];
        float4 ov = make_float4(o[rr][0] * invl, o[rr][1] * invl,
                                o[rr][2] * invl, o[rr][3] * invl);
        *(float4*)(ctx + (size_t)(row0 + rbase + rr) * HVTOT + h * DV + lane * 4) = ov;
    }
}

// ---------------- launcher ----------------
extern "C" void kernel_launch(void* const* d_in, const int* in_sizes, int n_in,
                              void* d_out, int out_size)
{
    const float* x    = (const float*)d_in[0];
    // d_in[1] = attention_mask: exactly causal -1e9 triu -> handled analytically
    const float* w_q  = (const float*)d_in[2];
    const float* w_k  = (const float*)d_in[3];
    const float* w_v  = (const float*)d_in[4];
    const float* w_o  = (const float*)d_in[5];
    const float* ln1w = (const float*)d_in[6];
    const float* ln1b = (const float*)d_in[7];
    const float* ln2w = (const float*)d_in[8];
    const float* ln2b = (const float*)d_in[9];
    const float* w1   = (const float*)d_in[10];
    const float* w2   = (const float*)d_in[11];
    float* out = (float*)d_out;

    float *h, *q, *k, *v, *ctx, *x2, *h2, *ffn;
    cudaGetSymbolAddress((void**)&h,   g_h);
    cudaGetSymbolAddress((void**)&q,   g_q);
    cudaGetSymbolAddress((void**)&k,   g_k);
    cudaGetSymbolAddress((void**)&v,   g_v);
    cudaGetSymbolAddress((void**)&ctx, g_ctx);
    cudaGetSymbolAddress((void**)&x2,  g_x2);
    cudaGetSymbolAddress((void**)&h2,  g_h2);
    cudaGetSymbolAddress((void**)&ffn, g_ffn);

    cudaFuncSetAttribute(flash_attn_kernel,
                         cudaFuncAttributeMaxDynamicSharedMemorySize, FA_SMEM_BYTES);
    cudaFuncSetAttribute(tf32_gemm_kernel,
                         cudaFuncAttributeMaxDynamicSharedMemorySize, G_SMEM_BYTES);

    // 1. ln1
    layernorm_kernel<<<SEQ, 256>>>(x, ln1w, ln1b, h);
    // 2-4. q, k, v projections
    tf32_gemm_kernel<<<dim3(QKD / 128, SEQ / 128), 256, G_SMEM_BYTES>>>(h, w_q, q, SEQ, QKD, HID, nullptr, 0);
    tf32_gemm_kernel<<<dim3(QKD / 128, SEQ / 128), 256, G_SMEM_BYTES>>>(h, w_k, k, SEQ, QKD, HID, nullptr, 0);
    tf32_gemm_kernel<<<dim3(HVTOT / 128, SEQ / 128), 256, G_SMEM_BYTES>>>(h, w_v, v, SEQ, HVTOT, HID, nullptr, 0);
    // 5. rope on q and k
    rope_kernel<<<dim3(SEQ, NH, 2), 32>>>(q, k);
    // 6. attention
    flash_attn_kernel<<<dim3(SEQ / 64, NH), 256, FA_SMEM_BYTES>>>(q, k, v, ctx);
    // 7. o projection + residual(x)
    tf32_gemm_kernel<<<dim3(HID / 128, SEQ / 128), 256, G_SMEM_BYTES>>>(ctx, w_o, x2, SEQ, HID, HVTOT, x, 0);
    // 8. ln2
    layernorm_kernel<<<SEQ, 256>>>(x2, ln2w, ln2b, h2);
    // 9. ffn up + silu
    tf32_gemm_kernel<<<dim3(FFN / 128, SEQ / 128), 256, G_SMEM_BYTES>>>(h2, w1, ffn, SEQ, FFN, HID, nullptr, 1);
    // 10. ffn down + residual(x2) -> out
    tf32_gemm_kernel<<<dim3(HID / 128, SEQ / 128), 256, G_SMEM_BYTES>>>(ffn, w2, out, SEQ, HID, FFN, x2, 0);
}

// round 14
// speedup vs baseline: 1.4259x; 1.1339x over previous
#include <cuda_runtime.h>
#include <cuda_bf16.h>
#include <math.h>
#include <stdint.h>

// ---------------- problem constants ----------------
constexpr int SEQ   = 2048;
constexpr int HID   = 4096;
constexpr int NH    = 32;
constexpr int DN    = 128;   // nope dim
constexpr int DR    = 64;    // rope dim
constexpr int DV    = 128;   // v dim
constexpr int QKD   = NH * (DN + DR);   // 6144
constexpr int HVTOT = NH * DV;          // 4096
constexpr int FFN   = 16384;

// ---------------- scratch (static device, no allocs) ----------------
__device__ float g_h  [SEQ * HID];
__device__ float g_q  [SEQ * QKD];
__device__ float g_k  [SEQ * QKD];
__device__ float g_v  [SEQ * HVTOT];
__device__ float g_ctx[SEQ * HVTOT];
__device__ float g_x2 [SEQ * HID];
__device__ float g_h2 [SEQ * HID];
__device__ float g_ffn[SEQ * FFN];

// ---------------- layernorm ----------------
__global__ void layernorm_kernel(const float* __restrict__ x,
                                 const float* __restrict__ wt,
                                 const float* __restrict__ bs,
                                 float* __restrict__ out)
{
    __shared__ float rs[8], rs2[8];
    int row = blockIdx.x, tid = threadIdx.x;
    const float4* xr = (const float4*)(x + (size_t)row * HID);
    float4 v[4];
    float s = 0.f, ss = 0.f;
#pragma unroll
    for (int it = 0; it < 4; it++) {
        v[it] = xr[tid + it * 256];
        s  += v[it].x + v[it].y + v[it].z + v[it].w;
        ss += v[it].x * v[it].x + v[it].y * v[it].y + v[it].z * v[it].z + v[it].w * v[it].w;
    }
#pragma unroll
    for (int off = 16; off; off >>= 1) {
        s  += __shfl_xor_sync(0xffffffffu, s, off);
        ss += __shfl_xor_sync(0xffffffffu, ss, off);
    }
    if ((tid & 31) == 0) { rs[tid >> 5] = s; rs2[tid >> 5] = ss; }
    __syncthreads();
    s = 0.f; ss = 0.f;
#pragma unroll
    for (int i = 0; i < 8; i++) { s += rs[i]; ss += rs2[i]; }
    float mean = s * (1.0f / HID);
    float var  = ss * (1.0f / HID) - mean * mean;
    float inv  = rsqrtf(var + 1e-6f);

    const float4* wv = (const float4*)wt;
    const float4* bv = (const float4*)bs;
    float4* ov = (float4*)(out + (size_t)row * HID);
#pragma unroll
    for (int it = 0; it < 4; it++) {
        float4 w4 = wv[tid + it * 256];
        float4 b4 = bv[tid + it * 256];
        float4 o4;
        o4.x = (v[it].x - mean) * inv * w4.x + b4.x;
        o4.y = (v[it].y - mean) * inv * w4.y + b4.y;
        o4.z = (v[it].z - mean) * inv * w4.z + b4.z;
        o4.w = (v[it].w - mean) * inv * w4.w + b4.w;
        ov[tid + it * 256] = o4;
    }
}

// ---------------- tf32 tensor-core GEMM ----------------
// C[M,N] = act(A[M,K] @ B[N,K]^T) (+ residual)
// 128x128x32 tile, 256 threads (8 warps, 2x4), warp tile 64x32 (4x4 m16n8k8),
// cp.async double buffering (2-stage, 2 CTAs/SM), single barrier per K-iter,
// cvt.rna.tf32 fragments, fp32 accumulate.  [R8 config + 1 barrier removed]
constexpr int GLD = 36;                  // smem row stride (floats), pad 4
constexpr int G_TILE_FLOATS = 128 * GLD; // per matrix per buffer
constexpr int G_SMEM_BYTES  = 2 * 2 * G_TILE_FLOATS * 4;  // 73728

__device__ __forceinline__ void cpa16(uint32_t dst, const float* src) {
    asm volatile("cp.async.cg.shared.global [%0], [%1], 16;\n" :: "r"(dst), "l"(src));
}
__device__ __forceinline__ uint32_t f2tf32(float f) {
    uint32_t u;
    asm("cvt.rna.tf32.f32 %0, %1;" : "=r"(u) : "f"(f));
    return u;
}
__device__ __forceinline__ void mma_tf32(float* c, const uint32_t* a, const uint32_t* b) {
    asm volatile(
        "mma.sync.aligned.m16n8k8.row.col.f32.tf32.tf32.f32 "
        "{%0,%1,%2,%3}, {%4,%5,%6,%7}, {%8,%9}, {%0,%1,%2,%3};\n"
        : "+f"(c[0]), "+f"(c[1]), "+f"(c[2]), "+f"(c[3])
        : "r"(a[0]), "r"(a[1]), "r"(a[2]), "r"(a[3]), "r"(b[0]), "r"(b[1]));
}

__global__ __launch_bounds__(256, 2)
void tf32_gemm_kernel(const float* __restrict__ A,
                      const float* __restrict__ B,
                      float* __restrict__ C,
                      int M, int N, int K,
                      const float* __restrict__ residual,
                      int act)
{
    extern __shared__ __align__(16) float gsm[];
    float* Asm = gsm;                       // [2][128][36]
    float* Bsm = gsm + 2 * G_TILE_FLOATS;   // [2][128][36]

    int tid  = threadIdx.x;
    int warp = tid >> 5, lane = tid & 31;
    int wm = warp >> 2;         // 0..1
    int wn = warp & 3;          // 0..3
    int grp = lane >> 2;        // 0..7
    int qid = lane & 3;         // 0..3
    int bm = blockIdx.y * 128;
    int bn = blockIdx.x * 128;

    const float* Ab = A + (size_t)bm * K;
    const float* Bb = B + (size_t)bn * K;

    uint32_t sA = (uint32_t)__cvta_generic_to_shared(Asm);
    uint32_t sB = (uint32_t)__cvta_generic_to_shared(Bsm);

    int ldrow = tid >> 3;          // 0..31
    int ldc4  = (tid & 7) * 4;     // k-offset in floats

    float acc[4][4][4];
#pragma unroll
    for (int mt = 0; mt < 4; mt++)
#pragma unroll
        for (int nt = 0; nt < 4; nt++)
#pragma unroll
            for (int r = 0; r < 4; r++) acc[mt][nt][r] = 0.f;

    int NT = K >> 5;   // K/32

    // prefetch tile 0 into buffer 0
    {
        uint32_t dA = sA, dB = sB;
#pragma unroll
        for (int i = 0; i < 4; i++) {
            int row = ldrow + i * 32;
            cpa16(dA + (row * GLD + ldc4) * 4, Ab + (size_t)row * K + ldc4);
            cpa16(dB + (row * GLD + ldc4) * 4, Bb + (size_t)row * K + ldc4);
        }
        asm volatile("cp.async.commit_group;\n");
    }

    for (int t = 0; t < NT; t++) {
        asm volatile("cp.async.wait_group 0;\n" ::: "memory");
        __syncthreads();
        // At this barrier every thread has finished compute(t-1), which read
        // buffer (t-1)&1 == (t+1)&1 — so prefetch(t+1) may overwrite it now.

        if (t + 1 < NT) {
            int k0n = (t + 1) << 5;
            uint32_t dA = sA + ((t + 1) & 1) * G_TILE_FLOATS * 4;
            uint32_t dB = sB + ((t + 1) & 1) * G_TILE_FLOATS * 4;
#pragma unroll
            for (int i = 0; i < 4; i++) {
                int row = ldrow + i * 32;
                cpa16(dA + (row * GLD + ldc4) * 4, Ab + (size_t)row * K + k0n + ldc4);
                cpa16(dB + (row * GLD + ldc4) * 4, Bb + (size_t)row * K + k0n + ldc4);
            }
            asm volatile("cp.async.commit_group;\n");
        }

        const float* Asb = Asm + (t & 1) * G_TILE_FLOATS;
        const float* Bsb = Bsm + (t & 1) * G_TILE_FLOATS;

#pragma unroll
        for (int ks = 0; ks < 4; ks++) {
            int k0 = ks * 8;
            uint32_t af[4][4], bf[4][2];
#pragma unroll
            for (int mt = 0; mt < 4; mt++) {
                const float* base = Asb + (wm * 64 + mt * 16 + grp) * GLD + k0 + qid;
                af[mt][0] = f2tf32(base[0]);
                af[mt][1] = f2tf32(base[8 * GLD]);
                af[mt][2] = f2tf32(base[4]);
                af[mt][3] = f2tf32(base[8 * GLD + 4]);
            }
#pragma unroll
            for (int nt = 0; nt < 4; nt++) {
                const float* base = Bsb + (wn * 32 + nt * 8 + grp) * GLD + k0 + qid;
                bf[nt][0] = f2tf32(base[0]);
                bf[nt][1] = f2tf32(base[4]);
            }
#pragma unroll
            for (int mt = 0; mt < 4; mt++)
#pragma unroll
                for (int nt = 0; nt < 4; nt++)
                    mma_tf32(acc[mt][nt], af[mt], bf[nt]);
        }
        // no trailing barrier: the next iteration's wait+sync provides the
        // producer/consumer ordering for buffer reuse.
    }

    // epilogue
#pragma unroll
    for (int mt = 0; mt < 4; mt++) {
#pragma unroll
        for (int half = 0; half < 2; half++) {
            int r = bm + wm * 64 + mt * 16 + grp + half * 8;
            size_t rowoff = (size_t)r * N;
#pragma unroll
            for (int nt = 0; nt < 4; nt++) {
                int c = bn + wn * 32 + nt * 8 + qid * 2;
                float v0 = acc[mt][nt][half * 2 + 0];
                float v1 = acc[mt][nt][half * 2 + 1];
                if (act == 1) {
                    v0 = v0 * (1.0f / (1.0f + __expf(-v0)));
                    v1 = v1 * (1.0f / (1.0f + __expf(-v1)));
                }
                if (residual != nullptr) {
                    float2 rv = *(const float2*)(residual + rowoff + c);
                    v0 += rv.x; v1 += rv.y;
                }
                *(float2*)(C + rowoff + c) = make_float2(v0, v1);
            }
        }
    }
}

// ---------------- RoPE (in place on q and k rope halves) ----------------
__global__ void rope_kernel(float* __restrict__ q, float* __restrict__ k)
{
    int s = blockIdx.x;
    int h = blockIdx.y;
    float* buf = (blockIdx.z == 0) ? q : k;
    int i = threadIdx.x;   // 0..31
    size_t base = (size_t)s * QKD + NH * DN + (size_t)h * DR;
    float invf = __powf(10000.0f, -(2.0f * (float)i) / (float)DR);
    float ang = (float)s * invf;
    float sn, cs;
    sincosf(ang, &sn, &cs);
    float x1 = buf[base + i];
    float x2 = buf[base + 32 + i];
    buf[base + i]      = x1 * cs - x2 * sn;
    buf[base + 32 + i] = x1 * sn + x2 * cs;
}

// ---------------- flash attention ----------------
// grid: (SEQ/64, NH). block 256. smem: Qt[192][68], Kt[192][68], Vs[64][128], Ps[64][64]
constexpr int QT_LD = 68;
constexpr int FA_SMEM_FLOATS = 192 * QT_LD * 2 + 64 * 128 + 64 * 64;
constexpr int FA_SMEM_BYTES  = FA_SMEM_FLOATS * 4;   // 153600

__global__ void flash_attn_kernel(const float* __restrict__ q,
                                  const float* __restrict__ k,
                                  const float* __restrict__ v,
                                  float* __restrict__ ctx)
{
    extern __shared__ __align__(16) float sm[];
    float* Qt = sm;                       // 192 x 68
    float* Kt = Qt + 192 * QT_LD;         // 192 x 68
    float* Vs = Kt + 192 * QT_LD;         // 64 x 128
    float* Ps = Vs + 64 * 128;            // 64 x 64

    int qb = blockIdx.x;
    int h  = blockIdx.y;
    int tid = threadIdx.x;
    int warp = tid >> 5;
    int lane = tid & 31;
    int tx = tid & 15;
    int ty = tid >> 4;
    int row0 = qb * 64;
    int rbase = warp * 8;

    const float scale_n = 0.08838834764831845f;  // 1/sqrt(128)
    const float scale_r = 0.125f;                // 1/sqrt(64)

    for (int e = tid; e < 64 * 128; e += 256) {
        int i = e >> 7, d = e & 127;
        Qt[d * QT_LD + i] = q[(size_t)(row0 + i) * QKD + h * DN + d] * scale_n;
    }
    for (int e = tid; e < 64 * 64; e += 256) {
        int i = e >> 6, d = e & 63;
        Qt[(128 + d) * QT_LD + i] =
            q[(size_t)(row0 + i) * QKD + NH * DN + h * DR + d] * scale_r;
    }

    float m_state[8], l_state[8];
    float o[8][4];
#pragma unroll
    for (int rr = 0; rr < 8; rr++) {
        m_state[rr] = -1e30f;
        l_state[rr] = 0.f;
        o[rr][0] = o[rr][1] = o[rr][2] = o[rr][3] = 0.f;
    }

    for (int kb = 0; kb <= qb; kb++) {
        int krow0 = kb * 64;
        __syncthreads();
        for (int e = tid; e < 64 * 128; e += 256) {
            int j = e >> 7, d = e & 127;
            Kt[d * QT_LD + j] = k[(size_t)(krow0 + j) * QKD + h * DN + d];
        }
        for (int e = tid; e < 64 * 64; e += 256) {
            int j = e >> 6, d = e & 63;
            Kt[(128 + d) * QT_LD + j] =
                k[(size_t)(krow0 + j) * QKD + NH * DN + h * DR + d];
        }
        for (int e = tid; e < 64 * 32; e += 256) {
            int j = e >> 5, d4 = e & 31;
            ((float4*)(Vs + j * 128))[d4] =
                *(const float4*)(v + (size_t)(krow0 + j) * HVTOT + h * DV + d4 * 4);
        }
        __syncthreads();

        float sc[4][4];
#pragma unroll
        for (int i = 0; i < 4; i++)
#pragma unroll
            for (int j = 0; j < 4; j++) sc[i][j] = 0.f;

#pragma unroll 4
        for (int d = 0; d < 192; d++) {
            float4 aq = *(const float4*)&Qt[d * QT_LD + ty * 4];
            float4 bk = *(const float4*)&Kt[d * QT_LD + tx * 4];
            float ar[4] = {aq.x, aq.y, aq.z, aq.w};
            float br[4] = {bk.x, bk.y, bk.z, bk.w};
#pragma unroll
            for (int i = 0; i < 4; i++)
#pragma unroll
                for (int j = 0; j < 4; j++)
                    sc[i][j] += ar[i] * br[j];
        }

        bool diag = (kb == qb);
#pragma unroll
        for (int i = 0; i < 4; i++) {
            int r = ty * 4 + i;
            float4 w4 = make_float4(sc[i][0], sc[i][1], sc[i][2], sc[i][3]);
            if (diag) {
                if (tx * 4 + 0 > r) w4.x = -1e30f;
                if (tx * 4 + 1 > r) w4.y = -1e30f;
                if (tx * 4 + 2 > r) w4.z = -1e30f;
                if (tx * 4 + 3 > r) w4.w = -1e30f;
            }
            *(float4*)&Ps[r * 64 + tx * 4] = w4;
        }
        __syncwarp();

        float alpha[8];
#pragma unroll
        for (int rr = 0; rr < 8; rr++) {
            int r = rbase + rr;
            float s0 = Ps[r * 64 + lane];
            float s1 = Ps[r * 64 + 32 + lane];
            float mx = fmaxf(s0, s1);
#pragma unroll
            for (int off = 16; off; off >>= 1)
                mx = fmaxf(mx, __shfl_xor_sync(0xffffffffu, mx, off));
            float m_new = fmaxf(m_state[rr], mx);
            float a_ = __expf(m_state[rr] - m_new);
            float e0 = __expf(s0 - m_new);
            float e1 = __expf(s1 - m_new);
            Ps[r * 64 + lane]      = e0;
            Ps[r * 64 + 32 + lane] = e1;
            float rsum = e0 + e1;
#pragma unroll
            for (int off = 16; off; off >>= 1)
                rsum += __shfl_xor_sync(0xffffffffu, rsum, off);
            l_state[rr] = l_state[rr] * a_ + rsum;
            m_state[rr] = m_new;
            alpha[rr] = a_;
        }
        __syncwarp();

#pragma unroll
        for (int rr = 0; rr < 8; rr++) {
            o[rr][0] *= alpha[rr]; o[rr][1] *= alpha[rr];
            o[rr][2] *= alpha[rr]; o[rr][3] *= alpha[rr];
        }
#pragma unroll 2
        for (int j = 0; j < 64; j++) {
            float4 vv = *(const float4*)&Vs[j * 128 + lane * 4];
#pragma unroll
            for (int rr = 0; rr < 8; rr++) {
                float p = Ps[(rbase + rr) * 64 + j];
                o[rr][0] += p * vv.x;
                o[rr][1] += p * vv.y;
                o[rr][2] += p * vv.z;
                o[rr][3] += p * vv.w;
            }
        }
    }

#pragma unroll
    for (int rr = 0; rr < 8; rr++) {
        float invl = 1.0f / l_state[rr];
        float4 ov = make_float4(o[rr][0] * invl, o[rr][1] * invl,
                                o[rr][2] * invl, o[rr][3] * invl);
        *(float4*)(ctx + (size_t)(row0 + rbase + rr) * HVTOT + h * DV + lane * 4) = ov;
    }
}

// ---------------- launcher ----------------
extern "C" void kernel_launch(void* const* d_in, const int* in_sizes, int n_in,
                              void* d_out, int out_size)
{
    const float* x    = (const float*)d_in[0];
    // d_in[1] = attention_mask: exactly causal -1e9 triu -> handled analytically
    const float* w_q  = (const float*)d_in[2];
    const float* w_k  = (const float*)d_in[3];
    const float* w_v  = (const float*)d_in[4];
    const float* w_o  = (const float*)d_in[5];
    const float* ln1w = (const float*)d_in[6];
    const float* ln1b = (const float*)d_in[7];
    const float* ln2w = (const float*)d_in[8];
    const float* ln2b = (const float*)d_in[9];
    const float* w1   = (const float*)d_in[10];
    const float* w2   = (const float*)d_in[11];
    float* out = (float*)d_out;

    float *h, *q, *k, *v, *ctx, *x2, *h2, *ffn;
    cudaGetSymbolAddress((void**)&h,   g_h);
    cudaGetSymbolAddress((void**)&q,   g_q);
    cudaGetSymbolAddress((void**)&k,   g_k);
    cudaGetSymbolAddress((void**)&v,   g_v);
    cudaGetSymbolAddress((void**)&ctx, g_ctx);
    cudaGetSymbolAddress((void**)&x2,  g_x2);
    cudaGetSymbolAddress((void**)&h2,  g_h2);
    cudaGetSymbolAddress((void**)&ffn, g_ffn);

    cudaFuncSetAttribute(flash_attn_kernel,
                         cudaFuncAttributeMaxDynamicSharedMemorySize, FA_SMEM_BYTES);
    cudaFuncSetAttribute(tf32_gemm_kernel,
                         cudaFuncAttributeMaxDynamicSharedMemorySize, G_SMEM_BYTES);

    // 1. ln1
    layernorm_kernel<<<SEQ, 256>>>(x, ln1w, ln1b, h);
    // 2-4. q, k, v projections
    tf32_gemm_kernel<<<dim3(QKD / 128, SEQ / 128), 256, G_SMEM_BYTES>>>(h, w_q, q, SEQ, QKD, HID, nullptr, 0);
    tf32_gemm_kernel<<<dim3(QKD / 128, SEQ / 128), 256, G_SMEM_BYTES>>>(h, w_k, k, SEQ, QKD, HID, nullptr, 0);
    tf32_gemm_kernel<<<dim3(HVTOT / 128, SEQ / 128), 256, G_SMEM_BYTES>>>(h, w_v, v, SEQ, HVTOT, HID, nullptr, 0);
    // 5. rope on q and k
    rope_kernel<<<dim3(SEQ, NH, 2), 32>>>(q, k);
    // 6. attention
    flash_attn_kernel<<<dim3(SEQ / 64, NH), 256, FA_SMEM_BYTES>>>(q, k, v, ctx);
    // 7. o projection + residual(x)
    tf32_gemm_kernel<<<dim3(HID / 128, SEQ / 128), 256, G_SMEM_BYTES>>>(ctx, w_o, x2, SEQ, HID, HVTOT, x, 0);
    // 8. ln2
    layernorm_kernel<<<SEQ, 256>>>(x2, ln2w, ln2b, h2);
    // 9. ffn up + silu
    tf32_gemm_kernel<<<dim3(FFN / 128, SEQ / 128), 256, G_SMEM_BYTES>>>(h2, w1, ffn, SEQ, FFN, HID, nullptr, 1);
    // 10. ffn down + residual(x2) -> out
    tf32_gemm_kernel<<<dim3(HID / 128, SEQ / 128), 256, G_SMEM_BYTES>>>(ffn, w2, out, SEQ, HID, FFN, x2, 0);
}

// round 16
// speedup vs baseline: 1.5046x; 1.0552x over previous
#include <cuda_runtime.h>
#include <cuda_bf16.h>
#include <math.h>
#include <stdint.h>

// ---------------- problem constants ----------------
constexpr int SEQ   = 2048;
constexpr int HID   = 4096;
constexpr int NH    = 32;
constexpr int DN    = 128;   // nope dim
constexpr int DR    = 64;    // rope dim
constexpr int DV    = 128;   // v dim
constexpr int QKD   = NH * (DN + DR);   // 6144
constexpr int HVTOT = NH * DV;          // 4096
constexpr int FFN   = 16384;

// ---------------- scratch (static device, no allocs) ----------------
__device__ float g_h  [SEQ * HID];
__device__ float g_q  [SEQ * QKD];
__device__ float g_k  [SEQ * QKD];
__device__ float g_v  [SEQ * HVTOT];
__device__ float g_ctx[SEQ * HVTOT];
__device__ float g_x2 [SEQ * HID];
__device__ float g_h2 [SEQ * HID];
__device__ float g_ffn[SEQ * FFN];

// ---------------- layernorm ----------------
__global__ void layernorm_kernel(const float* __restrict__ x,
                                 const float* __restrict__ wt,
                                 const float* __restrict__ bs,
                                 float* __restrict__ out)
{
    __shared__ float rs[8], rs2[8];
    int row = blockIdx.x, tid = threadIdx.x;
    const float4* xr = (const float4*)(x + (size_t)row * HID);
    float4 v[4];
    float s = 0.f, ss = 0.f;
#pragma unroll
    for (int it = 0; it < 4; it++) {
        v[it] = xr[tid + it * 256];
        s  += v[it].x + v[it].y + v[it].z + v[it].w;
        ss += v[it].x * v[it].x + v[it].y * v[it].y + v[it].z * v[it].z + v[it].w * v[it].w;
    }
#pragma unroll
    for (int off = 16; off; off >>= 1) {
        s  += __shfl_xor_sync(0xffffffffu, s, off);
        ss += __shfl_xor_sync(0xffffffffu, ss, off);
    }
    if ((tid & 31) == 0) { rs[tid >> 5] = s; rs2[tid >> 5] = ss; }
    __syncthreads();
    s = 0.f; ss = 0.f;
#pragma unroll
    for (int i = 0; i < 8; i++) { s += rs[i]; ss += rs2[i]; }
    float mean = s * (1.0f / HID);
    float var  = ss * (1.0f / HID) - mean * mean;
    float inv  = rsqrtf(var + 1e-6f);

    const float4* wv = (const float4*)wt;
    const float4* bv = (const float4*)bs;
    float4* ov = (float4*)(out + (size_t)row * HID);
#pragma unroll
    for (int it = 0; it < 4; it++) {
        float4 w4 = wv[tid + it * 256];
        float4 b4 = bv[tid + it * 256];
        float4 o4;
        o4.x = (v[it].x - mean) * inv * w4.x + b4.x;
        o4.y = (v[it].y - mean) * inv * w4.y + b4.y;
        o4.z = (v[it].z - mean) * inv * w4.z + b4.z;
        o4.w = (v[it].w - mean) * inv * w4.w + b4.w;
        ov[tid + it * 256] = o4;
    }
}

// ---------------- tf32 tensor-core GEMM (verified R14 config) ----------------
constexpr int GLD = 36;
constexpr int G_TILE_FLOATS = 128 * GLD;
constexpr int G_SMEM_BYTES  = 2 * 2 * G_TILE_FLOATS * 4;  // 73728

__device__ __forceinline__ void cpa16(uint32_t dst, const float* src) {
    asm volatile("cp.async.cg.shared.global [%0], [%1], 16;\n" :: "r"(dst), "l"(src));
}
__device__ __forceinline__ uint32_t f2tf32(float f) {
    uint32_t u;
    asm("cvt.rna.tf32.f32 %0, %1;" : "=r"(u) : "f"(f));
    return u;
}
__device__ __forceinline__ void mma_tf32(float* c, const uint32_t* a, const uint32_t* b) {
    asm volatile(
        "mma.sync.aligned.m16n8k8.row.col.f32.tf32.tf32.f32 "
        "{%0,%1,%2,%3}, {%4,%5,%6,%7}, {%8,%9}, {%0,%1,%2,%3};\n"
        : "+f"(c[0]), "+f"(c[1]), "+f"(c[2]), "+f"(c[3])
        : "r"(a[0]), "r"(a[1]), "r"(a[2]), "r"(a[3]), "r"(b[0]), "r"(b[1]));
}

__global__ __launch_bounds__(256, 2)
void tf32_gemm_kernel(const float* __restrict__ A,
                      const float* __restrict__ B,
                      float* __restrict__ C,
                      int M, int N, int K,
                      const float* __restrict__ residual,
                      int act)
{
    extern __shared__ __align__(16) float gsm[];
    float* Asm = gsm;
    float* Bsm = gsm + 2 * G_TILE_FLOATS;

    int tid  = threadIdx.x;
    int warp = tid >> 5, lane = tid & 31;
    int wm = warp >> 2;
    int wn = warp & 3;
    int grp = lane >> 2;
    int qid = lane & 3;
    int bm = blockIdx.y * 128;
    int bn = blockIdx.x * 128;

    const float* Ab = A + (size_t)bm * K;
    const float* Bb = B + (size_t)bn * K;

    uint32_t sA = (uint32_t)__cvta_generic_to_shared(Asm);
    uint32_t sB = (uint32_t)__cvta_generic_to_shared(Bsm);

    int ldrow = tid >> 3;
    int ldc4  = (tid & 7) * 4;

    float acc[4][4][4];
#pragma unroll
    for (int mt = 0; mt < 4; mt++)
#pragma unroll
        for (int nt = 0; nt < 4; nt++)
#pragma unroll
            for (int r = 0; r < 4; r++) acc[mt][nt][r] = 0.f;

    int NT = K >> 5;

    {
        uint32_t dA = sA, dB = sB;
#pragma unroll
        for (int i = 0; i < 4; i++) {
            int row = ldrow + i * 32;
            cpa16(dA + (row * GLD + ldc4) * 4, Ab + (size_t)row * K + ldc4);
            cpa16(dB + (row * GLD + ldc4) * 4, Bb + (size_t)row * K + ldc4);
        }
        asm volatile("cp.async.commit_group;\n");
    }

    for (int t = 0; t < NT; t++) {
        asm volatile("cp.async.wait_group 0;\n" ::: "memory");
        __syncthreads();

        if (t + 1 < NT) {
            int k0n = (t + 1) << 5;
            uint32_t dA = sA + ((t + 1) & 1) * G_TILE_FLOATS * 4;
            uint32_t dB = sB + ((t + 1) & 1) * G_TILE_FLOATS * 4;
#pragma unroll
            for (int i = 0; i < 4; i++) {
                int row = ldrow + i * 32;
                cpa16(dA + (row * GLD + ldc4) * 4, Ab + (size_t)row * K + k0n + ldc4);
                cpa16(dB + (row * GLD + ldc4) * 4, Bb + (size_t)row * K + k0n + ldc4);
            }
            asm volatile("cp.async.commit_group;\n");
        }

        const float* Asb = Asm + (t & 1) * G_TILE_FLOATS;
        const float* Bsb = Bsm + (t & 1) * G_TILE_FLOATS;

#pragma unroll
        for (int ks = 0; ks < 4; ks++) {
            int k0 = ks * 8;
            uint32_t af[4][4], bf[4][2];
#pragma unroll
            for (int mt = 0; mt < 4; mt++) {
                const float* base = Asb + (wm * 64 + mt * 16 + grp) * GLD + k0 + qid;
                af[mt][0] = f2tf32(base[0]);
                af[mt][1] = f2tf32(base[8 * GLD]);
                af[mt][2] = f2tf32(base[4]);
                af[mt][3] = f2tf32(base[8 * GLD + 4]);
            }
#pragma unroll
            for (int nt = 0; nt < 4; nt++) {
                const float* base = Bsb + (wn * 32 + nt * 8 + grp) * GLD + k0 + qid;
                bf[nt][0] = f2tf32(base[0]);
                bf[nt][1] = f2tf32(base[4]);
            }
#pragma unroll
            for (int mt = 0; mt < 4; mt++)
#pragma unroll
                for (int nt = 0; nt < 4; nt++)
                    mma_tf32(acc[mt][nt], af[mt], bf[nt]);
        }
    }

#pragma unroll
    for (int mt = 0; mt < 4; mt++) {
#pragma unroll
        for (int half = 0; half < 2; half++) {
            int r = bm + wm * 64 + mt * 16 + grp + half * 8;
            size_t rowoff = (size_t)r * N;
#pragma unroll
            for (int nt = 0; nt < 4; nt++) {
                int c = bn + wn * 32 + nt * 8 + qid * 2;
                float v0 = acc[mt][nt][half * 2 + 0];
                float v1 = acc[mt][nt][half * 2 + 1];
                if (act == 1) {
                    v0 = v0 * (1.0f / (1.0f + __expf(-v0)));
                    v1 = v1 * (1.0f / (1.0f + __expf(-v1)));
                }
                if (residual != nullptr) {
                    float2 rv = *(const float2*)(residual + rowoff + c);
                    v0 += rv.x; v1 += rv.y;
                }
                *(float2*)(C + rowoff + c) = make_float2(v0, v1);
            }
        }
    }
}

// ---------------- RoPE ----------------
__global__ void rope_kernel(float* __restrict__ q, float* __restrict__ k)
{
    int s = blockIdx.x;
    int h = blockIdx.y;
    float* buf = (blockIdx.z == 0) ? q : k;
    int i = threadIdx.x;
    size_t base = (size_t)s * QKD + NH * DN + (size_t)h * DR;
    float invf = __powf(10000.0f, -(2.0f * (float)i) / (float)DR);
    float ang = (float)s * invf;
    float sn, cs;
    sincosf(ang, &sn, &cs);
    float x1 = buf[base + i];
    float x2 = buf[base + 32 + i];
    buf[base + i]      = x1 * cs - x2 * sn;
    buf[base + 32 + i] = x1 * sn + x2 * cs;
}

// ---------------- flash attention (tf32 MMA for S and PV) ----------------
// grid (SEQ/64, NH), 256 threads (8 warps).
// Qs/Ks: [64][196] row-major K-contig (196 = 4 mod 32 -> conflict-free frags)
// Vt: [128][68] (d-major), Ps: [64][68], alpha_s/l_s: [64]
constexpr int QLD = 196;
constexpr int PLD = 68;
constexpr int VLD = 68;
constexpr int FA_SMEM_FLOATS = 64 * QLD * 2 + 128 * VLD + 64 * PLD + 128;
constexpr int FA_SMEM_BYTES  = FA_SMEM_FLOATS * 4;   // ~153KB

__global__ __launch_bounds__(256, 1)
void flash_attn_kernel(const float* __restrict__ q,
                       const float* __restrict__ k,
                       const float* __restrict__ v,
                       float* __restrict__ ctx)
{
    extern __shared__ __align__(16) float sm[];
    float* Qs = sm;                      // 64 x 196
    float* Ks = Qs + 64 * QLD;           // 64 x 196
    float* Vt = Ks + 64 * QLD;           // 128 x 68
    float* Ps = Vt + 128 * VLD;          // 64 x 68
    float* alpha_s = Ps + 64 * PLD;      // 64
    float* l_s     = alpha_s + 64;       // 64

    int qb = blockIdx.x;
    int h  = blockIdx.y;
    int tid = threadIdx.x;
    int warp = tid >> 5, lane = tid & 31;
    int wm = warp >> 2;       // 0..1  (rows)
    int wn = warp & 3;        // 0..3  (cols)
    int grp = lane >> 2;      // 0..7
    int qid = lane & 3;       // 0..3
    int row0 = qb * 64;
    int rbase = warp * 8;

    const float scale_n = 0.08838834764831845f;  // 1/sqrt(128)
    const float scale_r = 0.125f;                // 1/sqrt(64)

    // load Q tile (row-major, pre-scaled)
    for (int e = tid; e < 64 * 128; e += 256) {
        int i = e >> 7, d = e & 127;
        Qs[i * QLD + d] = q[(size_t)(row0 + i) * QKD + h * DN + d] * scale_n;
    }
    for (int e = tid; e < 64 * 64; e += 256) {
        int i = e >> 6, d = e & 63;
        Qs[i * QLD + 128 + d] =
            q[(size_t)(row0 + i) * QKD + NH * DN + h * DR + d] * scale_r;
    }

    float m_state[8], l_state[8];
#pragma unroll
    for (int rr = 0; rr < 8; rr++) { m_state[rr] = -1e30f; l_state[rr] = 0.f; }

    float o[2][4][4];   // [mt][nt][reg]  rows wm*32+mt*16+{grp,grp+8}, cols wn*32+nt*8+2qid..
#pragma unroll
    for (int mt = 0; mt < 2; mt++)
#pragma unroll
        for (int nt = 0; nt < 4; nt++)
#pragma unroll
            for (int r = 0; r < 4; r++) o[mt][nt][r] = 0.f;

    for (int kb = 0; kb <= qb; kb++) {
        int krow0 = kb * 64;
        __syncthreads();   // prev PV done; safe to overwrite Ks/Vt

        // K tile (row-major) + V tile transposed (d-major)
        for (int e = tid; e < 64 * 128; e += 256) {
            int j = e >> 7, d = e & 127;
            Ks[j * QLD + d] = k[(size_t)(krow0 + j) * QKD + h * DN + d];
        }
        for (int e = tid; e < 64 * 64; e += 256) {
            int j = e >> 6, d = e & 63;
            Ks[j * QLD + 128 + d] =
                k[(size_t)(krow0 + j) * QKD + NH * DN + h * DR + d];
        }
        for (int e = tid; e < 64 * 128; e += 256) {
            int j = e >> 7, d = e & 127;
            Vt[d * VLD + j] = v[(size_t)(krow0 + j) * HVTOT + h * DV + d];
        }
        __syncthreads();

        // ---- S = Q K^T via mma (warp tile 32x16: mt=2, nt=2) ----
        float sc[2][2][4];
#pragma unroll
        for (int mt = 0; mt < 2; mt++)
#pragma unroll
            for (int nt = 0; nt < 2; nt++)
#pragma unroll
                for (int r = 0; r < 4; r++) sc[mt][nt][r] = 0.f;

#pragma unroll
        for (int ks = 0; ks < 24; ks++) {
            int k0 = ks * 8;
            uint32_t af[2][4], bf[2][2];
#pragma unroll
            for (int mt = 0; mt < 2; mt++) {
                const float* base = Qs + (wm * 32 + mt * 16 + grp) * QLD + k0 + qid;
                af[mt][0] = f2tf32(base[0]);
                af[mt][1] = f2tf32(base[8 * QLD]);
                af[mt][2] = f2tf32(base[4]);
                af[mt][3] = f2tf32(base[8 * QLD + 4]);
            }
#pragma unroll
            for (int nt = 0; nt < 2; nt++) {
                const float* base = Ks + (wn * 16 + nt * 8 + grp) * QLD + k0 + qid;
                bf[nt][0] = f2tf32(base[0]);
                bf[nt][1] = f2tf32(base[4]);
            }
#pragma unroll
            for (int mt = 0; mt < 2; mt++)
#pragma unroll
                for (int nt = 0; nt < 2; nt++)
                    mma_tf32(sc[mt][nt], af[mt], bf[nt]);
        }

        // store S fragments to Ps
#pragma unroll
        for (int mt = 0; mt < 2; mt++) {
            int r0 = wm * 32 + mt * 16 + grp;
#pragma unroll
            for (int nt = 0; nt < 2; nt++) {
                int c0 = wn * 16 + nt * 8 + qid * 2;
                *(float2*)&Ps[r0 * PLD + c0]       = make_float2(sc[mt][nt][0], sc[mt][nt][1]);
                *(float2*)&Ps[(r0 + 8) * PLD + c0] = make_float2(sc[mt][nt][2], sc[mt][nt][3]);
            }
        }
        __syncthreads();

        // ---- online softmax (per-warp rows, causal mask applied here) ----
        bool diag = (kb == qb);
#pragma unroll
        for (int rr = 0; rr < 8; rr++) {
            int r = rbase + rr;
            float s0 = Ps[r * PLD + lane];
            float s1 = Ps[r * PLD + 32 + lane];
            if (diag) {
                if (lane > r)      s0 = -1e30f;
                if (32 + lane > r) s1 = -1e30f;
            }
            float mx = fmaxf(s0, s1);
#pragma unroll
            for (int off = 16; off; off >>= 1)
                mx = fmaxf(mx, __shfl_xor_sync(0xffffffffu, mx, off));
            float m_new = fmaxf(m_state[rr], mx);
            float a_ = __expf(m_state[rr] - m_new);
            float e0 = __expf(s0 - m_new);
            float e1 = __expf(s1 - m_new);
            Ps[r * PLD + lane]      = e0;
            Ps[r * PLD + 32 + lane] = e1;
            float rsum = e0 + e1;
#pragma unroll
            for (int off = 16; off; off >>= 1)
                rsum += __shfl_xor_sync(0xffffffffu, rsum, off);
            l_state[rr] = l_state[rr] * a_ + rsum;
            m_state[rr] = m_new;
            if (lane == 0) alpha_s[r] = a_;
        }
        __syncthreads();

        // ---- rescale O, then O += P V via mma (warp tile 32x32: mt=2, nt=4) ----
#pragma unroll
        for (int mt = 0; mt < 2; mt++) {
            int r0 = wm * 32 + mt * 16 + grp;
            float a0 = alpha_s[r0];
            float a1 = alpha_s[r0 + 8];
#pragma unroll
            for (int nt = 0; nt < 4; nt++) {
                o[mt][nt][0] *= a0; o[mt][nt][1] *= a0;
                o[mt][nt][2] *= a1; o[mt][nt][3] *= a1;
            }
        }
#pragma unroll
        for (int ks = 0; ks < 8; ks++) {
            int k0 = ks * 8;
            uint32_t af[2][4], bf[4][2];
#pragma unroll
            for (int mt = 0; mt < 2; mt++) {
                const float* base = Ps + (wm * 32 + mt * 16 + grp) * PLD + k0 + qid;
                af[mt][0] = f2tf32(base[0]);
                af[mt][1] = f2tf32(base[8 * PLD]);
                af[mt][2] = f2tf32(base[4]);
                af[mt][3] = f2tf32(base[8 * PLD + 4]);
            }
#pragma unroll
            for (int nt = 0; nt < 4; nt++) {
                const float* base = Vt + (wn * 32 + nt * 8 + grp) * VLD + k0 + qid;
                bf[nt][0] = f2tf32(base[0]);
                bf[nt][1] = f2tf32(base[4]);
            }
#pragma unroll
            for (int mt = 0; mt < 2; mt++)
#pragma unroll
                for (int nt = 0; nt < 4; nt++)
                    mma_tf32(o[mt][nt], af[mt], bf[nt]);
        }
    }

    // publish final l per row
    if (lane == 0) {
#pragma unroll
        for (int rr = 0; rr < 8; rr++) l_s[rbase + rr] = l_state[rr];
    }
    __syncthreads();

    // normalize + write ctx
#pragma unroll
    for (int mt = 0; mt < 2; mt++) {
        int r0 = wm * 32 + mt * 16 + grp;
        float il0 = 1.0f / l_s[r0];
        float il1 = 1.0f / l_s[r0 + 8];
#pragma unroll
        for (int nt = 0; nt < 4; nt++) {
            int c = h * DV + wn * 32 + nt * 8 + qid * 2;
            *(float2*)(ctx + (size_t)(row0 + r0) * HVTOT + c) =
                make_float2(o[mt][nt][0] * il0, o[mt][nt][1] * il0);
            *(float2*)(ctx + (size_t)(row0 + r0 + 8) * HVTOT + c) =
                make_float2(o[mt][nt][2] * il1, o[mt][nt][3] * il1);
        }
    }
}

// ---------------- launcher ----------------
extern "C" void kernel_launch(void* const* d_in, const int* in_sizes, int n_in,
                              void* d_out, int out_size)
{
    const float* x    = (const float*)d_in[0];
    const float* w_q  = (const float*)d_in[2];
    const float* w_k  = (const float*)d_in[3];
    const float* w_v  = (const float*)d_in[4];
    const float* w_o  = (const float*)d_in[5];
    const float* ln1w = (const float*)d_in[6];
    const float* ln1b = (const float*)d_in[7];
    const float* ln2w = (const float*)d_in[8];
    const float* ln2b = (const float*)d_in[9];
    const float* w1   = (const float*)d_in[10];
    const float* w2   = (const float*)d_in[11];
    float* out = (float*)d_out;

    float *h, *q, *k, *v, *ctx, *x2, *h2, *ffn;
    cudaGetSymbolAddress((void**)&h,   g_h);
    cudaGetSymbolAddress((void**)&q,   g_q);
    cudaGetSymbolAddress((void**)&k,   g_k);
    cudaGetSymbolAddress((void**)&v,   g_v);
    cudaGetSymbolAddress((void**)&ctx, g_ctx);
    cudaGetSymbolAddress((void**)&x2,  g_x2);
    cudaGetSymbolAddress((void**)&h2,  g_h2);
    cudaGetSymbolAddress((void**)&ffn, g_ffn);

    cudaFuncSetAttribute(flash_attn_kernel,
                         cudaFuncAttributeMaxDynamicSharedMemorySize, FA_SMEM_BYTES);
    cudaFuncSetAttribute(tf32_gemm_kernel,
                         cudaFuncAttributeMaxDynamicSharedMemorySize, G_SMEM_BYTES);

    // 1. ln1
    layernorm_kernel<<<SEQ, 256>>>(x, ln1w, ln1b, h);
    // 2-4. q, k, v projections
    tf32_gemm_kernel<<<dim3(QKD / 128, SEQ / 128), 256, G_SMEM_BYTES>>>(h, w_q, q, SEQ, QKD, HID, nullptr, 0);
    tf32_gemm_kernel<<<dim3(QKD / 128, SEQ / 128), 256, G_SMEM_BYTES>>>(h, w_k, k, SEQ, QKD, HID, nullptr, 0);
    tf32_gemm_kernel<<<dim3(HVTOT / 128, SEQ / 128), 256, G_SMEM_BYTES>>>(h, w_v, v, SEQ, HVTOT, HID, nullptr, 0);
    // 5. rope on q and k
    rope_kernel<<<dim3(SEQ, NH, 2), 32>>>(q, k);
    // 6. attention (tf32 MMA)
    flash_attn_kernel<<<dim3(SEQ / 64, NH), 256, FA_SMEM_BYTES>>>(q, k, v, ctx);
    // 7. o projection + residual(x)
    tf32_gemm_kernel<<<dim3(HID / 128, SEQ / 128), 256, G_SMEM_BYTES>>>(ctx, w_o, x2, SEQ, HID, HVTOT, x, 0);
    // 8. ln2
    layernorm_kernel<<<SEQ, 256>>>(x2, ln2w, ln2b, h2);
    // 9. ffn up + silu
    tf32_gemm_kernel<<<dim3(FFN / 128, SEQ / 128), 256, G_SMEM_BYTES>>>(h2, w1, ffn, SEQ, FFN, HID, nullptr, 1);
    // 10. ffn down + residual(x2) -> out
    tf32_gemm_kernel<<<dim3(HID / 128, SEQ / 128), 256, G_SMEM_BYTES>>>(ffn, w2, out, SEQ, HID, FFN, x2, 0);
}